// round 10
// baseline (speedup 1.0000x reference)
#include <cuda_runtime.h>
#include <math.h>

#define T_   16
#define B_   8
#define H_   224
#define W_   224
#define C_   3
#define CH_  32
#define OUT_ 10
#define NIMG (T_*B_)     // 128
#define KX   113         // W/2+1

typedef unsigned long long ull;

// ---- packed f32x2 helpers ----
__device__ __forceinline__ ull pack2(float lo, float hi) {
    ull r;
    asm("mov.b64 %0, {%1, %2};" : "=l"(r) : "f"(lo), "f"(hi));
    return r;
}
__device__ __forceinline__ void unpack2(ull v, float& lo, float& hi) {
    asm("mov.b64 {%0, %1}, %2;" : "=f"(lo), "=f"(hi) : "l"(v));
}
__device__ __forceinline__ ull fma2(ull a, ull b, ull c) {
    ull d;
    asm("fma.rn.f32x2 %0, %1, %2, %3;" : "=l"(d) : "l"(a), "l"(b), "l"(c));
    return d;
}

// ---- scratch ----
__device__ float g_G1re[NIMG*H_*KX];   // stage1 output (img, y, kx)
__device__ float g_G1im[NIMG*H_*KX];
__device__ float g_mag [NIMG*H_*KX];   // log1p(|spec|)  (img, ky, kx)
__device__ ull   g_twp  [224];         // (cos, sin)
__device__ ull   g_twcc [224];         // (cos, cos)
__device__ ull   g_twss [224];         // (sin, sin)
__device__ int   g_spk[T_*B_*CH_];     // spike counts per (t,b,ch)
__device__ float g_epart[1024];        // per-block mag partial sums

// conv weights/bias in constant memory: warp-uniform, compile-time offsets
// -> LDCU uniform path, off the L1tex/smem crossbar.
// c_w2[r*8 + qq] = ulonglong2 covering channel pairs (4qq..4qq+3) of tap r
// (raw copy of HWIO convw: tap r = (dy*3+dx)*4 + ci, co contiguous).
__constant__ ulonglong2 c_w2[288];     // 36 taps x 8 ulonglong2 (4608 B)
__constant__ ull        c_b[16];       // 32 bias floats as 16 pairs

// ---------------------------------------------------------------------------
__global__ void k_init() {
    int tid = blockIdx.x*blockDim.x + threadIdx.x;
    if (tid < 224) {
        double a = (2.0*M_PI*(double)tid)/224.0;
        float c = (float)cos(a), s = (float)sin(a);
        g_twp [tid] = pack2(c, s);
        g_twcc[tid] = pack2(c, c);
        g_twss[tid] = pack2(s, s);
    }
    for (int i = tid; i < T_*B_*CH_; i += gridDim.x*blockDim.x) g_spk[i] = 0;
    for (int i = tid; i < 1024; i += gridDim.x*blockDim.x) g_epart[i] = 0.f;
}

// ---------------------------------------------------------------------------
// Stage 1: row DFT with real-input x-fold. (unchanged — passing, known perf)
__global__ void __launch_bounds__(128) k_stage1(const float* __restrict__ x) {
    __shared__ ull   sd[32][111];        // pack2(S, D), x-1 indexed
    __shared__ ull   twp[224];
    __shared__ float ge0[32], ge1[32];   // g[0], g[112] per row
    int img = blockIdx.y;
    int y0  = blockIdx.x * 32;
    int tid = threadIdx.x;
    for (int i = tid; i < 224; i += 128) twp[i] = g_twp[i];
    const float* xb = x + (size_t)img * H_ * W_ * C_;
    for (int i = tid; i < 32*112; i += 128) {
        int yl = i / 112, xx = i % 112;
        int gy = y0 + yl;
        const float* rowp = xb + (size_t)gy * W_ * 3;
        if (xx == 0) {
            ge0[yl] = (rowp[0] + rowp[1] + rowp[2]) * (1.0f/3.0f);
            const float* q = rowp + 112*3;
            ge1[yl] = (q[0] + q[1] + q[2]) * (1.0f/3.0f);
        } else {
            const float* pa = rowp + xx*3;
            const float* pb = rowp + (224 - xx)*3;
            float a = (pa[0] + pa[1] + pa[2]) * (1.0f/3.0f);
            float b = (pb[0] + pb[1] + pb[2]) * (1.0f/3.0f);
            sd[yl][xx-1] = pack2(a + b, a - b);
        }
    }
    __syncthreads();

    int g  = tid >> 2;          // 0..31
    int yt = tid & 3;           // 0..3
    int r0 = yt * 8;
    int k0 = g, k1 = g+32, k2 = g+64, k3 = g+96;
    ull P[32];
    #pragma unroll
    for (int i = 0; i < 32; i++) P[i] = 0;
    int m0 = k0, m1 = k1, m2 = k2, m3 = k3;

    for (int xi = 0; xi < 111; xi++) {
        ull s0 = sd[r0  ][xi], s1 = sd[r0+1][xi];
        ull s2 = sd[r0+2][xi], s3 = sd[r0+3][xi];
        ull s4 = sd[r0+4][xi], s5 = sd[r0+5][xi];
        ull s6 = sd[r0+6][xi], s7 = sd[r0+7][xi];
        ull t;
        t = twp[m0];
        P[0] = fma2(s0,t,P[0]); P[1] = fma2(s1,t,P[1]);
        P[2] = fma2(s2,t,P[2]); P[3] = fma2(s3,t,P[3]);
        P[4] = fma2(s4,t,P[4]); P[5] = fma2(s5,t,P[5]);
        P[6] = fma2(s6,t,P[6]); P[7] = fma2(s7,t,P[7]);
        m0 += k0; if (m0 >= 224) m0 -= 224;
        t = twp[m1];
        P[8]  = fma2(s0,t,P[8]);  P[9]  = fma2(s1,t,P[9]);
        P[10] = fma2(s2,t,P[10]); P[11] = fma2(s3,t,P[11]);
        P[12] = fma2(s4,t,P[12]); P[13] = fma2(s5,t,P[13]);
        P[14] = fma2(s6,t,P[14]); P[15] = fma2(s7,t,P[15]);
        m1 += k1; if (m1 >= 224) m1 -= 224;
        t = twp[m2];
        P[16] = fma2(s0,t,P[16]); P[17] = fma2(s1,t,P[17]);
        P[18] = fma2(s2,t,P[18]); P[19] = fma2(s3,t,P[19]);
        P[20] = fma2(s4,t,P[20]); P[21] = fma2(s5,t,P[21]);
        P[22] = fma2(s6,t,P[22]); P[23] = fma2(s7,t,P[23]);
        m2 += k2; if (m2 >= 224) m2 -= 224;
        t = twp[m3];
        P[24] = fma2(s0,t,P[24]); P[25] = fma2(s1,t,P[25]);
        P[26] = fma2(s2,t,P[26]); P[27] = fma2(s3,t,P[27]);
        P[28] = fma2(s4,t,P[28]); P[29] = fma2(s5,t,P[29]);
        P[30] = fma2(s6,t,P[30]); P[31] = fma2(s7,t,P[31]);
        m3 += k3; if (m3 >= 224) m3 -= 224;
    }

    float par = (g & 1) ? -1.0f : 1.0f;
    #pragma unroll
    for (int j = 0; j < 4; j++) {
        int k = g + 32*j;
        if (k < KX) {
            #pragma unroll
            for (int r = 0; r < 8; r++) {
                float sc, ds;
                unpack2(P[j*8 + r], sc, ds);
                int row = r0 + r;
                size_t idx = (size_t)img*H_*KX + (size_t)(y0 + row)*KX + k;
                g_G1re[idx] = sc + ge0[row] + par*ge1[row];
                g_G1im[idx] = -ds;
            }
        }
    }
}

// ---------------------------------------------------------------------------
// Stage 2: column DFT with double fold (y and ky). (unchanged from R9)
__global__ void __launch_bounds__(224) k_stage2() {
    __shared__ ulonglong2 sSre[56][8], sSim[56][8], sDre[56][8], sDim[56][8];
    __shared__ ulonglong2 tp2[224];                // (cc, ss)
    __shared__ float red[256];
    int img = blockIdx.y;
    int kxb = blockIdx.x * 32;
    int tid = threadIdx.x;
    int kyg = tid >> 3;             // 0..27
    int kxs = tid & 7;
    for (int i = tid; i < 224; i += 224)
        tp2[i] = make_ulonglong2(g_twcc[i], g_twss[i]);
    if (tid < 32) red[224 + tid] = 0.f;

    const float* inre = g_G1re + (size_t)img*H_*KX;
    const float* inim = g_G1im + (size_t)img*H_*KX;

    ull P1a[4], P2a[4], P3a[4], P4a[4];
    ull P1b[4], P2b[4], P3b[4], P4b[4];
    int m[4], kyv[4];
    #pragma unroll
    for (int j = 0; j < 4; j++) {
        P1a[j]=P2a[j]=P3a[j]=P4a[j]=0;
        P1b[j]=P2b[j]=P3b[j]=P4b[j]=0;
        kyv[j] = 1 + kyg + 28*j;
        m[j] = kyv[j];
    }
    ull A0reA = 0, A0imA = 0, A0reB = 0, A0imB = 0;   // ky=0 (kyg==0 lanes)
    const ull ONE2 = pack2(1.0f, 1.0f);

    for (int chunk = 0; chunk < 2; chunk++) {
        int yb   = 1 + 56*chunk;
        int ycnt = chunk ? 55 : 56;
        __syncthreads();
        for (int i = tid; i < ycnt*8; i += 224) {
            int yy = i >> 3, ks = i & 7;
            int y = yb + yy, ym = 224 - y;
            int k0 = kxb + 4*ks;
            float reS[4], imS[4], reD[4], imD[4];
            #pragma unroll
            for (int q = 0; q < 4; q++) {
                int kx = k0 + q;
                float ra  = (kx < KX) ? inre[y*KX + kx]  : 0.f;
                float ia  = (kx < KX) ? inim[y*KX + kx]  : 0.f;
                float rb  = (kx < KX) ? inre[ym*KX + kx] : 0.f;
                float ib  = (kx < KX) ? inim[ym*KX + kx] : 0.f;
                reS[q] = ra + rb;  reD[q] = ra - rb;
                imS[q] = ia + ib;  imD[q] = ia - ib;
            }
            sSre[yy][ks] = make_ulonglong2(pack2(reS[0], reS[1]), pack2(reS[2], reS[3]));
            sDre[yy][ks] = make_ulonglong2(pack2(reD[0], reD[1]), pack2(reD[2], reD[3]));
            sSim[yy][ks] = make_ulonglong2(pack2(imS[0], imS[1]), pack2(imS[2], imS[3]));
            sDim[yy][ks] = make_ulonglong2(pack2(imD[0], imD[1]), pack2(imD[2], imD[3]));
        }
        __syncthreads();
        for (int yy = 0; yy < ycnt; yy++) {
            ulonglong2 sre = sSre[yy][kxs];
            ulonglong2 sim = sSim[yy][kxs];
            ulonglong2 dre = sDre[yy][kxs];
            ulonglong2 dim = sDim[yy][kxs];
            if (kyg == 0) {
                A0reA = fma2(sre.x, ONE2, A0reA);
                A0imA = fma2(sim.x, ONE2, A0imA);
                A0reB = fma2(sre.y, ONE2, A0reB);
                A0imB = fma2(sim.y, ONE2, A0imB);
            }
            #pragma unroll
            for (int j = 0; j < 4; j++) {
                ulonglong2 tw = tp2[m[j]];
                P1a[j] = fma2(sre.x, tw.x, P1a[j]);
                P2a[j] = fma2(dim.x, tw.y, P2a[j]);
                P3a[j] = fma2(sim.x, tw.x, P3a[j]);
                P4a[j] = fma2(dre.x, tw.y, P4a[j]);
                P1b[j] = fma2(sre.y, tw.x, P1b[j]);
                P2b[j] = fma2(dim.y, tw.y, P2b[j]);
                P3b[j] = fma2(sim.y, tw.x, P3b[j]);
                P4b[j] = fma2(dre.y, tw.y, P4b[j]);
                m[j] += kyv[j]; if (m[j] >= 224) m[j] -= 224;
            }
        }
    }

    // edge rows y=0, y=112 (4 consecutive kx for this thread)
    int k0 = kxb + 4*kxs;
    float G0re[4], G0im[4], G1re[4], G1im[4];
    #pragma unroll
    for (int q = 0; q < 4; q++) {
        int kx = k0 + q;
        G0re[q] = (kx < KX) ? inre[kx]          : 0.f;
        G0im[q] = (kx < KX) ? inim[kx]          : 0.f;
        G1re[q] = (kx < KX) ? inre[112*KX + kx] : 0.f;
        G1im[q] = (kx < KX) ? inim[112*KX + kx] : 0.f;
    }

    float esum = 0.f;
    float* outm = g_mag + (size_t)img*H_*KX;
    #pragma unroll
    for (int j = 0; j < 4; j++) {
        int ky = kyv[j];
        float par = (ky & 1) ? -1.0f : 1.0f;
        float p1[4], p2[4], p3[4], p4[4];
        unpack2(P1a[j], p1[0], p1[1]); unpack2(P1b[j], p1[2], p1[3]);
        unpack2(P2a[j], p2[0], p2[1]); unpack2(P2b[j], p2[2], p2[3]);
        unpack2(P3a[j], p3[0], p3[1]); unpack2(P3b[j], p3[2], p3[3]);
        unpack2(P4a[j], p4[0], p4[1]); unpack2(P4b[j], p4[2], p4[3]);
        #pragma unroll
        for (int q = 0; q < 4; q++) {
            int kx = k0 + q;
            if (kx < KX) {
                float Ere = G0re[q] + par*G1re[q];
                float Eim = G0im[q] + par*G1im[q];
                float re = p1[q] + p2[q] + Ere, im = p3[q] - p4[q] + Eim;
                float v = log1pf(sqrtf(fmaf(re, re, im*im)));
                outm[ky*KX + kx] = v; esum += v;
                if (ky != 112) {
                    float re2 = p1[q] - p2[q] + Ere, im2 = p3[q] + p4[q] + Eim;
                    float v2 = log1pf(sqrtf(fmaf(re2, re2, im2*im2)));
                    outm[(224-ky)*KX + kx] = v2; esum += v2;
                }
            }
        }
    }
    if (kyg == 0) {
        float a[4], ii[4];
        unpack2(A0reA, a[0], a[1]); unpack2(A0reB, a[2], a[3]);
        unpack2(A0imA, ii[0], ii[1]); unpack2(A0imB, ii[2], ii[3]);
        #pragma unroll
        for (int q = 0; q < 4; q++) {
            int kx = k0 + q;
            if (kx < KX) {
                float re = a[q] + G0re[q] + G1re[q];
                float im = ii[q] + G0im[q] + G1im[q];
                float v = log1pf(sqrtf(fmaf(re, re, im*im)));
                outm[kx] = v; esum += v;
            }
        }
    }
    red[tid] = esum; __syncthreads();
    for (int s = 128; s > 0; s >>= 1) {
        if (tid < s && tid + s < 256) red[tid] += red[tid+s];
        __syncthreads();
    }
    if (tid == 0) g_epart[img*4 + blockIdx.x] = red[0];
}

// ---------------------------------------------------------------------------
// Fused conv3x3(4->32) + LIF. Channel split via blockIdx.z (2 halves of 16).
// Thread = 2 vertical px x 16 ch. Weights/bias in CONSTANT memory (uniform
// LDCU path — off the smem crossbar); smem carries only the input tile.
__global__ void __launch_bounds__(256, 4) k_convlif(const float* __restrict__ x) {
    __shared__ ull  tile[2][4][34][19];   // packed (v,v)
    __shared__ int  cnt[2][16];
    int tid = threadIdx.x;
    int b   = blockIdx.y;
    int coh = blockIdx.z;                  // channel half
    int tileid = blockIdx.x;               // 0..97
    int ty0 = (tileid / 14) * 32, tx0 = (tileid % 14) * 16;
    int ty  = tid >> 4;                    // 0..15 -> rows 2ty, 2ty+1
    int tx  = tid & 15;
    int lane = tid & 31;
    int r0 = 2*ty;
    int cbase = coh * 4;                   // ulonglong2 offset of this half

    if (tid < 32) cnt[tid >> 4][tid & 15] = 0;

    const ull betaP = pack2(0.9f, 0.9f);
    ull VA[8], VB[8];
    #pragma unroll
    for (int c = 0; c < 8; c++) { VA[c] = 0; VB[c] = 0; }

    auto loadTile = [&](int buf, int img) {
        const float* xb = x + (size_t)img * H_ * W_ * C_;
        const float* magb = g_mag + (size_t)img * H_ * KX;
        for (int i = tid; i < 34*18; i += 256) {
            int yy = i / 18, xx = i % 18;
            int gy = ty0 + yy - 1, gx = tx0 + xx - 1;
            float v0=0.f, v1=0.f, v2=0.f, v3=0.f;
            if (gy >= 0 && gy < H_ && gx >= 0 && gx < W_) {
                const float* p = xb + ((size_t)gy*W_ + gx)*3;
                v0 = p[0]; v1 = p[1]; v2 = p[2];
                float xsrc = (gx + 0.5f) * (113.0f/224.0f) - 0.5f;
                float fi = floorf(xsrc);
                int i0 = (int)fi; float f = xsrc - fi;
                const float* mrow = magb + gy*KX;
                if (i0 < 0)            v3 = mrow[0];
                else if (i0 >= KX - 1) v3 = mrow[KX-1];
                else { float a = mrow[i0]; v3 = fmaf(f, mrow[i0+1] - a, a); }
            }
            tile[buf][0][yy][xx] = pack2(v0, v0);
            tile[buf][1][yy][xx] = pack2(v1, v1);
            tile[buf][2][yy][xx] = pack2(v2, v2);
            tile[buf][3][yy][xx] = pack2(v3, v3);
        }
    };

    loadTile(0, 0*B_ + b);
    __syncthreads();               // tile[0] + cnt ready
    int cur = 0;
    for (int t = 0; t < T_; t++) {
        if (t + 1 < T_) loadTile(1 - cur, (t+1)*B_ + b);

        #pragma unroll
        for (int c = 0; c < 8; c++) {
            ull bb = c_b[coh*8 + c];
            VA[c] = fma2(VA[c], betaP, bb);
            VB[c] = fma2(VB[c], betaP, bb);
        }
        #pragma unroll
        for (int dx = 0; dx < 3; dx++) {
            #pragma unroll
            for (int ci = 0; ci < 4; ci++) {
                ull rr0 = tile[cur][ci][r0    ][tx + dx];
                ull rr1 = tile[cur][ci][r0 + 1][tx + dx];
                ull rr2 = tile[cur][ci][r0 + 2][tx + dx];
                ull rr3 = tile[cur][ci][r0 + 3][tx + dx];
                #pragma unroll
                for (int dy = 0; dy < 3; dy++) {
                    ull va = (dy == 0) ? rr0 : ((dy == 1) ? rr1 : rr2);
                    ull vb = (dy == 0) ? rr1 : ((dy == 1) ? rr2 : rr3);
                    const ulonglong2* w2 = &c_w2[((dy*3 + dx)*4 + ci)*8 + cbase];
                    ulonglong2 w;
                    w = w2[0];
                    VA[0] = fma2(va, w.x, VA[0]); VB[0] = fma2(vb, w.x, VB[0]);
                    VA[1] = fma2(va, w.y, VA[1]); VB[1] = fma2(vb, w.y, VB[1]);
                    w = w2[1];
                    VA[2] = fma2(va, w.x, VA[2]); VB[2] = fma2(vb, w.x, VB[2]);
                    VA[3] = fma2(va, w.y, VA[3]); VB[3] = fma2(vb, w.y, VB[3]);
                    w = w2[2];
                    VA[4] = fma2(va, w.x, VA[4]); VB[4] = fma2(vb, w.x, VB[4]);
                    VA[5] = fma2(va, w.y, VA[5]); VB[5] = fma2(vb, w.y, VB[5]);
                    w = w2[3];
                    VA[6] = fma2(va, w.x, VA[6]); VB[6] = fma2(vb, w.x, VB[6]);
                    VA[7] = fma2(va, w.y, VA[7]); VB[7] = fma2(vb, w.y, VB[7]);
                }
            }
        }
        // spike + soft reset (16 local channels per pixel)
        unsigned mk0 = 0, mk1 = 0;
        #pragma unroll
        for (int c = 0; c < 8; c++) {
            float a0, a1;
            unpack2(VA[c], a0, a1);
            bool s0 = (a0 - 1.0f) > 0.f, s1 = (a1 - 1.0f) > 0.f;
            a0 -= s0 ? 1.0f : 0.0f; a1 -= s1 ? 1.0f : 0.0f;
            VA[c] = pack2(a0, a1);
            mk0 |= (s0?1u:0u) << (2*c); mk0 |= (s1?1u:0u) << (2*c+1);
            unpack2(VB[c], a0, a1);
            s0 = (a0 - 1.0f) > 0.f; s1 = (a1 - 1.0f) > 0.f;
            a0 -= s0 ? 1.0f : 0.0f; a1 -= s1 ? 1.0f : 0.0f;
            VB[c] = pack2(a0, a1);
            mk1 |= (s0?1u:0u) << (2*c); mk1 |= (s1?1u:0u) << (2*c+1);
        }
        int myc = 0;
        #pragma unroll
        for (int c = 0; c < 16; c++) {
            unsigned b0 = __ballot_sync(0xffffffffu, (mk0 >> c) & 1u);
            unsigned b1 = __ballot_sync(0xffffffffu, (mk1 >> c) & 1u);
            if (lane == c) myc = __popc(b0) + __popc(b1);
        }
        if (lane < 16) atomicAdd(&cnt[t & 1][lane], myc);
        __syncthreads();   // cnt[t&1] done; tile[cur] reads done; tile[1-cur] stores done
        if (tid < 16) {
            atomicAdd(&g_spk[(t*B_ + b)*32 + coh*16 + tid], cnt[t & 1][tid]);
            cnt[t & 1][tid] = 0;   // safe: next use is t+2, a sync at t+1 intervenes
        }
        cur ^= 1;
    }
}

// ---------------------------------------------------------------------------
__global__ void k_final(const float* __restrict__ head_w,
                        const float* __restrict__ head_b,
                        float* __restrict__ out) {
    __shared__ float red[256];
    int tid = threadIdx.x;
    float acc = 0.f;
    for (int i = tid; i < T_*B_*CH_; i += 256) acc += (float)g_spk[i];
    red[tid] = acc; __syncthreads();
    for (int s = 128; s > 0; s >>= 1) { if (tid < s) red[tid] += red[tid+s]; __syncthreads(); }
    float totspk = red[0];
    __syncthreads();
    float e = 0.f;
    for (int i = tid; i < 1024; i += 256) e += g_epart[i];
    red[tid] = e; __syncthreads();
    for (int s = 128; s > 0; s >>= 1) { if (tid < s) red[tid] += red[tid+s]; __syncthreads(); }
    float etot = red[0];

    for (int idx = tid; idx < T_*B_*OUT_; idx += 256) {
        int o = idx % OUT_; int tb = idx / OUT_;
        const int* sp = &g_spk[tb*32];
        float s = 0.f;
        #pragma unroll
        for (int c = 0; c < 32; c++) s = fmaf((float)sp[c], head_w[c*OUT_ + o], s);
        out[80 + idx] = s * (1.0f/(float)(H_*W_)) + head_b[o];
    }
    __syncthreads();
    for (int idx = tid; idx < B_*OUT_; idx += 256) {
        int b = idx / OUT_, o = idx % OUT_;
        float s = 0.f;
        for (int t = 0; t < T_; t++) s += out[80 + ((t*B_ + b)*OUT_ + o)];
        out[idx] = s * (1.0f/(float)T_);
    }
    if (tid == 0) {
        out[80 + T_*B_*OUT_]     = totspk / ((float)T_*B_*H_*W_*CH_);
        out[80 + T_*B_*OUT_ + 1] = etot   / ((float)NIMG*H_*KX);
    }
}

// ---------------------------------------------------------------------------
extern "C" void kernel_launch(void* const* d_in, const int* in_sizes, int n_in,
                              void* d_out, int out_size) {
    const float* x     = (const float*)d_in[0];   // (16,8,224,224,3)
    const float* convw = (const float*)d_in[1];   // (3,3,4,32)
    const float* convb = (const float*)d_in[2];   // (32,)
    const float* headw = (const float*)d_in[3];   // (32,10)
    const float* headb = (const float*)d_in[4];   // (10,)
    float* out = (float*)d_out;

    // stage conv weights/bias into constant memory (async D2D; capturable)
    cudaMemcpyToSymbolAsync(c_w2, convw, 36*16*sizeof(ull), 0,
                            cudaMemcpyDeviceToDevice);
    cudaMemcpyToSymbolAsync(c_b, convb, 16*sizeof(ull), 0,
                            cudaMemcpyDeviceToDevice);

    k_init<<<16, 256>>>();
    { dim3 g(7,  NIMG);    k_stage1<<<g, 128>>>(x); }
    { dim3 g(4,  NIMG);    k_stage2<<<g, 224>>>(); }
    { dim3 g(98, B_, 2);   k_convlif<<<g, 256>>>(x); }
    k_final<<<1, 256>>>(headw, headb, out);
}

// round 12
// speedup vs baseline: 1.3824x; 1.3824x over previous
#include <cuda_runtime.h>
#include <math.h>

#define T_   16
#define B_   8
#define H_   224
#define W_   224
#define C_   3
#define CH_  32
#define OUT_ 10
#define NIMG (T_*B_)     // 128
#define KX   113         // W/2+1

typedef unsigned long long ull;

// ---- packed f32x2 helpers ----
__device__ __forceinline__ ull pack2(float lo, float hi) {
    ull r;
    asm("mov.b64 %0, {%1, %2};" : "=l"(r) : "f"(lo), "f"(hi));
    return r;
}
__device__ __forceinline__ void unpack2(ull v, float& lo, float& hi) {
    asm("mov.b64 {%0, %1}, %2;" : "=f"(lo), "=f"(hi) : "l"(v));
}
__device__ __forceinline__ ull fma2(ull a, ull b, ull c) {
    ull d;
    asm("fma.rn.f32x2 %0, %1, %2, %3;" : "=l"(d) : "l"(a), "l"(b), "l"(c));
    return d;
}

// ---- scratch ----
__device__ float g_G1re[NIMG*H_*KX];   // stage1 output (img, y, kx)
__device__ float g_G1im[NIMG*H_*KX];
__device__ float g_mag [NIMG*H_*KX];   // log1p(|spec|)  (img, ky, kx)
__device__ ull   g_twp  [224];         // (cos, sin)
__device__ ull   g_twcc [224];         // (cos, cos)
__device__ ull   g_twss [224];         // (sin, sin)
__device__ int   g_spk[T_*B_*CH_];     // spike counts per (t,b,ch)
__device__ float g_epart[1024];        // per-block mag partial sums

// ---------------------------------------------------------------------------
__global__ void k_init() {
    int tid = blockIdx.x*blockDim.x + threadIdx.x;
    if (tid < 224) {
        double a = (2.0*M_PI*(double)tid)/224.0;
        float c = (float)cos(a), s = (float)sin(a);
        g_twp [tid] = pack2(c, s);
        g_twcc[tid] = pack2(c, c);
        g_twss[tid] = pack2(s, s);
    }
    for (int i = tid; i < T_*B_*CH_; i += gridDim.x*blockDim.x) g_spk[i] = 0;
    for (int i = tid; i < 1024; i += gridDim.x*blockDim.x) g_epart[i] = 0.f;
}

// ---------------------------------------------------------------------------
// Stage 1: row DFT with real-input x-fold. (unchanged — passing, known perf)
__global__ void __launch_bounds__(128) k_stage1(const float* __restrict__ x) {
    __shared__ ull   sd[32][111];        // pack2(S, D), x-1 indexed
    __shared__ ull   twp[224];
    __shared__ float ge0[32], ge1[32];   // g[0], g[112] per row
    int img = blockIdx.y;
    int y0  = blockIdx.x * 32;
    int tid = threadIdx.x;
    for (int i = tid; i < 224; i += 128) twp[i] = g_twp[i];
    const float* xb = x + (size_t)img * H_ * W_ * C_;
    for (int i = tid; i < 32*112; i += 128) {
        int yl = i / 112, xx = i % 112;
        int gy = y0 + yl;
        const float* rowp = xb + (size_t)gy * W_ * 3;
        if (xx == 0) {
            ge0[yl] = (rowp[0] + rowp[1] + rowp[2]) * (1.0f/3.0f);
            const float* q = rowp + 112*3;
            ge1[yl] = (q[0] + q[1] + q[2]) * (1.0f/3.0f);
        } else {
            const float* pa = rowp + xx*3;
            const float* pb = rowp + (224 - xx)*3;
            float a = (pa[0] + pa[1] + pa[2]) * (1.0f/3.0f);
            float b = (pb[0] + pb[1] + pb[2]) * (1.0f/3.0f);
            sd[yl][xx-1] = pack2(a + b, a - b);
        }
    }
    __syncthreads();

    int g  = tid >> 2;          // 0..31
    int yt = tid & 3;           // 0..3
    int r0 = yt * 8;
    int k0 = g, k1 = g+32, k2 = g+64, k3 = g+96;
    ull P[32];
    #pragma unroll
    for (int i = 0; i < 32; i++) P[i] = 0;
    int m0 = k0, m1 = k1, m2 = k2, m3 = k3;

    for (int xi = 0; xi < 111; xi++) {
        ull s0 = sd[r0  ][xi], s1 = sd[r0+1][xi];
        ull s2 = sd[r0+2][xi], s3 = sd[r0+3][xi];
        ull s4 = sd[r0+4][xi], s5 = sd[r0+5][xi];
        ull s6 = sd[r0+6][xi], s7 = sd[r0+7][xi];
        ull t;
        t = twp[m0];
        P[0] = fma2(s0,t,P[0]); P[1] = fma2(s1,t,P[1]);
        P[2] = fma2(s2,t,P[2]); P[3] = fma2(s3,t,P[3]);
        P[4] = fma2(s4,t,P[4]); P[5] = fma2(s5,t,P[5]);
        P[6] = fma2(s6,t,P[6]); P[7] = fma2(s7,t,P[7]);
        m0 += k0; if (m0 >= 224) m0 -= 224;
        t = twp[m1];
        P[8]  = fma2(s0,t,P[8]);  P[9]  = fma2(s1,t,P[9]);
        P[10] = fma2(s2,t,P[10]); P[11] = fma2(s3,t,P[11]);
        P[12] = fma2(s4,t,P[12]); P[13] = fma2(s5,t,P[13]);
        P[14] = fma2(s6,t,P[14]); P[15] = fma2(s7,t,P[15]);
        m1 += k1; if (m1 >= 224) m1 -= 224;
        t = twp[m2];
        P[16] = fma2(s0,t,P[16]); P[17] = fma2(s1,t,P[17]);
        P[18] = fma2(s2,t,P[18]); P[19] = fma2(s3,t,P[19]);
        P[20] = fma2(s4,t,P[20]); P[21] = fma2(s5,t,P[21]);
        P[22] = fma2(s6,t,P[22]); P[23] = fma2(s7,t,P[23]);
        m2 += k2; if (m2 >= 224) m2 -= 224;
        t = twp[m3];
        P[24] = fma2(s0,t,P[24]); P[25] = fma2(s1,t,P[25]);
        P[26] = fma2(s2,t,P[26]); P[27] = fma2(s3,t,P[27]);
        P[28] = fma2(s4,t,P[28]); P[29] = fma2(s5,t,P[29]);
        P[30] = fma2(s6,t,P[30]); P[31] = fma2(s7,t,P[31]);
        m3 += k3; if (m3 >= 224) m3 -= 224;
    }

    float par = (g & 1) ? -1.0f : 1.0f;
    #pragma unroll
    for (int j = 0; j < 4; j++) {
        int k = g + 32*j;
        if (k < KX) {
            #pragma unroll
            for (int r = 0; r < 8; r++) {
                float sc, ds;
                unpack2(P[j*8 + r], sc, ds);
                int row = r0 + r;
                size_t idx = (size_t)img*H_*KX + (size_t)(y0 + row)*KX + k;
                g_G1re[idx] = sc + ge0[row] + par*ge1[row];
                g_G1im[idx] = -ds;
            }
        }
    }
}

// ---------------------------------------------------------------------------
// Stage 2: column DFT with double fold (y and ky). (unchanged from R9)
__global__ void __launch_bounds__(224) k_stage2() {
    __shared__ ulonglong2 sSre[56][8], sSim[56][8], sDre[56][8], sDim[56][8];
    __shared__ ulonglong2 tp2[224];                // (cc, ss)
    __shared__ float red[256];
    int img = blockIdx.y;
    int kxb = blockIdx.x * 32;
    int tid = threadIdx.x;
    int kyg = tid >> 3;             // 0..27
    int kxs = tid & 7;
    for (int i = tid; i < 224; i += 224)
        tp2[i] = make_ulonglong2(g_twcc[i], g_twss[i]);
    if (tid < 32) red[224 + tid] = 0.f;

    const float* inre = g_G1re + (size_t)img*H_*KX;
    const float* inim = g_G1im + (size_t)img*H_*KX;

    ull P1a[4], P2a[4], P3a[4], P4a[4];
    ull P1b[4], P2b[4], P3b[4], P4b[4];
    int m[4], kyv[4];
    #pragma unroll
    for (int j = 0; j < 4; j++) {
        P1a[j]=P2a[j]=P3a[j]=P4a[j]=0;
        P1b[j]=P2b[j]=P3b[j]=P4b[j]=0;
        kyv[j] = 1 + kyg + 28*j;
        m[j] = kyv[j];
    }
    ull A0reA = 0, A0imA = 0, A0reB = 0, A0imB = 0;   // ky=0 (kyg==0 lanes)
    const ull ONE2 = pack2(1.0f, 1.0f);

    for (int chunk = 0; chunk < 2; chunk++) {
        int yb   = 1 + 56*chunk;
        int ycnt = chunk ? 55 : 56;
        __syncthreads();
        for (int i = tid; i < ycnt*8; i += 224) {
            int yy = i >> 3, ks = i & 7;
            int y = yb + yy, ym = 224 - y;
            int k0 = kxb + 4*ks;
            float reS[4], imS[4], reD[4], imD[4];
            #pragma unroll
            for (int q = 0; q < 4; q++) {
                int kx = k0 + q;
                float ra  = (kx < KX) ? inre[y*KX + kx]  : 0.f;
                float ia  = (kx < KX) ? inim[y*KX + kx]  : 0.f;
                float rb  = (kx < KX) ? inre[ym*KX + kx] : 0.f;
                float ib  = (kx < KX) ? inim[ym*KX + kx] : 0.f;
                reS[q] = ra + rb;  reD[q] = ra - rb;
                imS[q] = ia + ib;  imD[q] = ia - ib;
            }
            sSre[yy][ks] = make_ulonglong2(pack2(reS[0], reS[1]), pack2(reS[2], reS[3]));
            sDre[yy][ks] = make_ulonglong2(pack2(reD[0], reD[1]), pack2(reD[2], reD[3]));
            sSim[yy][ks] = make_ulonglong2(pack2(imS[0], imS[1]), pack2(imS[2], imS[3]));
            sDim[yy][ks] = make_ulonglong2(pack2(imD[0], imD[1]), pack2(imD[2], imD[3]));
        }
        __syncthreads();
        for (int yy = 0; yy < ycnt; yy++) {
            ulonglong2 sre = sSre[yy][kxs];
            ulonglong2 sim = sSim[yy][kxs];
            ulonglong2 dre = sDre[yy][kxs];
            ulonglong2 dim = sDim[yy][kxs];
            if (kyg == 0) {
                A0reA = fma2(sre.x, ONE2, A0reA);
                A0imA = fma2(sim.x, ONE2, A0imA);
                A0reB = fma2(sre.y, ONE2, A0reB);
                A0imB = fma2(sim.y, ONE2, A0imB);
            }
            #pragma unroll
            for (int j = 0; j < 4; j++) {
                ulonglong2 tw = tp2[m[j]];
                P1a[j] = fma2(sre.x, tw.x, P1a[j]);
                P2a[j] = fma2(dim.x, tw.y, P2a[j]);
                P3a[j] = fma2(sim.x, tw.x, P3a[j]);
                P4a[j] = fma2(dre.x, tw.y, P4a[j]);
                P1b[j] = fma2(sre.y, tw.x, P1b[j]);
                P2b[j] = fma2(dim.y, tw.y, P2b[j]);
                P3b[j] = fma2(sim.y, tw.x, P3b[j]);
                P4b[j] = fma2(dre.y, tw.y, P4b[j]);
                m[j] += kyv[j]; if (m[j] >= 224) m[j] -= 224;
            }
        }
    }

    // edge rows y=0, y=112 (4 consecutive kx for this thread)
    int k0 = kxb + 4*kxs;
    float G0re[4], G0im[4], G1re[4], G1im[4];
    #pragma unroll
    for (int q = 0; q < 4; q++) {
        int kx = k0 + q;
        G0re[q] = (kx < KX) ? inre[kx]          : 0.f;
        G0im[q] = (kx < KX) ? inim[kx]          : 0.f;
        G1re[q] = (kx < KX) ? inre[112*KX + kx] : 0.f;
        G1im[q] = (kx < KX) ? inim[112*KX + kx] : 0.f;
    }

    float esum = 0.f;
    float* outm = g_mag + (size_t)img*H_*KX;
    #pragma unroll
    for (int j = 0; j < 4; j++) {
        int ky = kyv[j];
        float par = (ky & 1) ? -1.0f : 1.0f;
        float p1[4], p2[4], p3[4], p4[4];
        unpack2(P1a[j], p1[0], p1[1]); unpack2(P1b[j], p1[2], p1[3]);
        unpack2(P2a[j], p2[0], p2[1]); unpack2(P2b[j], p2[2], p2[3]);
        unpack2(P3a[j], p3[0], p3[1]); unpack2(P3b[j], p3[2], p3[3]);
        unpack2(P4a[j], p4[0], p4[1]); unpack2(P4b[j], p4[2], p4[3]);
        #pragma unroll
        for (int q = 0; q < 4; q++) {
            int kx = k0 + q;
            if (kx < KX) {
                float Ere = G0re[q] + par*G1re[q];
                float Eim = G0im[q] + par*G1im[q];
                float re = p1[q] + p2[q] + Ere, im = p3[q] - p4[q] + Eim;
                float v = log1pf(sqrtf(fmaf(re, re, im*im)));
                outm[ky*KX + kx] = v; esum += v;
                if (ky != 112) {
                    float re2 = p1[q] - p2[q] + Ere, im2 = p3[q] + p4[q] + Eim;
                    float v2 = log1pf(sqrtf(fmaf(re2, re2, im2*im2)));
                    outm[(224-ky)*KX + kx] = v2; esum += v2;
                }
            }
        }
    }
    if (kyg == 0) {
        float a[4], ii[4];
        unpack2(A0reA, a[0], a[1]); unpack2(A0reB, a[2], a[3]);
        unpack2(A0imA, ii[0], ii[1]); unpack2(A0imB, ii[2], ii[3]);
        #pragma unroll
        for (int q = 0; q < 4; q++) {
            int kx = k0 + q;
            if (kx < KX) {
                float re = a[q] + G0re[q] + G1re[q];
                float im = ii[q] + G0im[q] + G1im[q];
                float v = log1pf(sqrtf(fmaf(re, re, im*im)));
                outm[kx] = v; esum += v;
            }
        }
    }
    red[tid] = esum; __syncthreads();
    for (int s = 128; s > 0; s >>= 1) {
        if (tid < s && tid + s < 256) red[tid] += red[tid+s];
        __syncthreads();
    }
    if (tid == 0) g_epart[img*4 + blockIdx.x] = red[0];
}

// ---------------------------------------------------------------------------
// Fused conv3x3(4->32) + LIF. Channel split via blockIdx.z (2 halves of 16).
// Thread = 2 HORIZONTALLY-adjacent px (cols 2tx, 2tx+1) x 16 ch: the 4 tile
// columns per (ci,row) come from 2 aligned LDS.128. Weights in smem as
// LDS.128. Spike counts via REDUX.SUM + direct global atomics (no smem cnt).
__global__ void __launch_bounds__(256, 4) k_convlif(const float* __restrict__ x,
                                                    const float* __restrict__ convw,
                                                    const float* __restrict__ convb) {
    __shared__ ulonglong2 wshP2[36*4];    // [tap r = p*4+ci][q] = ch-pairs 2q,2q+1
    __shared__ ull  bshP[8];
    __shared__ ull  tile[2][4][18][36];   // packed (v,v); halo 18 rows x 34 cols (pad 36)
    int tid = threadIdx.x;
    int b   = blockIdx.y;
    int coh = blockIdx.z;                  // channel half
    int tileid = blockIdx.x;               // 0..97  (14 row-tiles x 7 col-tiles)
    int ty0 = (tileid / 7) * 16, tx0 = (tileid % 7) * 32;
    int ty  = tid >> 4;                    // 0..15  (pixel row)
    int tx  = tid & 15;                    // cols 2tx, 2tx+1
    int lane = tid & 31;

    const ull* wsrc = (const ull*)convw;   // [36][16] ull (co contiguous)
    const ull* bsrc = (const ull*)convb;
    for (int i = tid; i < 144; i += 256) {
        int r = i >> 2, q = i & 3;
        wshP2[i] = make_ulonglong2(wsrc[r*16 + coh*8 + 2*q],
                                   wsrc[r*16 + coh*8 + 2*q + 1]);
    }
    if (tid < 8)  bshP[tid] = bsrc[coh*8 + tid];

    const ull betaP = pack2(0.9f, 0.9f);
    ull VA[8], VB[8];                      // px A (col 2tx), px B (col 2tx+1)
    #pragma unroll
    for (int c = 0; c < 8; c++) { VA[c] = 0; VB[c] = 0; }

    auto loadTile = [&](int buf, int img) {
        const float* xb = x + (size_t)img * H_ * W_ * C_;
        const float* magb = g_mag + (size_t)img * H_ * KX;
        for (int i = tid; i < 18*34; i += 256) {
            int yy = i / 34, xx = i % 34;
            int gy = ty0 + yy - 1, gx = tx0 + xx - 1;
            float v0=0.f, v1=0.f, v2=0.f, v3=0.f;
            if (gy >= 0 && gy < H_ && gx >= 0 && gx < W_) {
                const float* p = xb + ((size_t)gy*W_ + gx)*3;
                v0 = p[0]; v1 = p[1]; v2 = p[2];
                float xsrc = (gx + 0.5f) * (113.0f/224.0f) - 0.5f;
                float fi = floorf(xsrc);
                int i0 = (int)fi; float f = xsrc - fi;
                const float* mrow = magb + gy*KX;
                if (i0 < 0)            v3 = mrow[0];
                else if (i0 >= KX - 1) v3 = mrow[KX-1];
                else { float a = mrow[i0]; v3 = fmaf(f, mrow[i0+1] - a, a); }
            }
            tile[buf][0][yy][xx] = pack2(v0, v0);
            tile[buf][1][yy][xx] = pack2(v1, v1);
            tile[buf][2][yy][xx] = pack2(v2, v2);
            tile[buf][3][yy][xx] = pack2(v3, v3);
        }
    };

    loadTile(0, 0*B_ + b);
    __syncthreads();               // tile[0] + weights ready
    int cur = 0;
    for (int t = 0; t < T_; t++) {
        if (t + 1 < T_) loadTile(1 - cur, (t+1)*B_ + b);

        #pragma unroll
        for (int c = 0; c < 8; c++) {
            ull bb = bshP[c];
            VA[c] = fma2(VA[c], betaP, bb);
            VB[c] = fma2(VB[c], betaP, bb);
        }
        #pragma unroll
        for (int dy = 0; dy < 3; dy++) {
            #pragma unroll
            for (int ci = 0; ci < 4; ci++) {
                // cols 2tx .. 2tx+3 of halo row ty+dy (px A taps: +0..2, B: +1..3)
                const ull* rowp = &tile[cur][ci][ty + dy][2*tx];
                ulonglong2 u01 = *(const ulonglong2*)(rowp);
                ulonglong2 u23 = *(const ulonglong2*)(rowp + 2);
                ull cv[4] = {u01.x, u01.y, u23.x, u23.y};
                #pragma unroll
                for (int dx = 0; dx < 3; dx++) {
                    ull va = cv[dx];
                    ull vb = cv[dx + 1];
                    const ulonglong2* w2 = &wshP2[((dy*3 + dx)*4 + ci)*4];
                    ulonglong2 w;
                    w = w2[0];
                    VA[0] = fma2(va, w.x, VA[0]); VB[0] = fma2(vb, w.x, VB[0]);
                    VA[1] = fma2(va, w.y, VA[1]); VB[1] = fma2(vb, w.y, VB[1]);
                    w = w2[1];
                    VA[2] = fma2(va, w.x, VA[2]); VB[2] = fma2(vb, w.x, VB[2]);
                    VA[3] = fma2(va, w.y, VA[3]); VB[3] = fma2(vb, w.y, VB[3]);
                    w = w2[2];
                    VA[4] = fma2(va, w.x, VA[4]); VB[4] = fma2(vb, w.x, VB[4]);
                    VA[5] = fma2(va, w.y, VA[5]); VB[5] = fma2(vb, w.y, VB[5]);
                    w = w2[3];
                    VA[6] = fma2(va, w.x, VA[6]); VB[6] = fma2(vb, w.x, VB[6]);
                    VA[7] = fma2(va, w.y, VA[7]); VB[7] = fma2(vb, w.y, VB[7]);
                }
            }
        }
        // spike + soft reset; masks bit c = channel c
        unsigned mkA = 0, mkB = 0;
        #pragma unroll
        for (int c = 0; c < 8; c++) {
            float a0, a1;
            unpack2(VA[c], a0, a1);
            bool s0 = (a0 - 1.0f) > 0.f, s1 = (a1 - 1.0f) > 0.f;
            a0 -= s0 ? 1.0f : 0.0f; a1 -= s1 ? 1.0f : 0.0f;
            VA[c] = pack2(a0, a1);
            mkA |= (s0?1u:0u) << (2*c); mkA |= (s1?1u:0u) << (2*c+1);
            unpack2(VB[c], a0, a1);
            s0 = (a0 - 1.0f) > 0.f; s1 = (a1 - 1.0f) > 0.f;
            a0 -= s0 ? 1.0f : 0.0f; a1 -= s1 ? 1.0f : 0.0f;
            VB[c] = pack2(a0, a1);
            mkB |= (s0?1u:0u) << (2*c); mkB |= (s1?1u:0u) << (2*c+1);
        }
        // per-channel warp sums via REDUX; lane c keeps channel c
        unsigned mysum = 0;
        #pragma unroll
        for (int c = 0; c < 16; c++) {
            unsigned v = ((mkA >> c) & 1u) + ((mkB >> c) & 1u);
            unsigned s = __reduce_add_sync(0xffffffffu, v);
            if (lane == c) mysum = s;
        }
        if (lane < 16)
            atomicAdd(&g_spk[(t*B_ + b)*32 + coh*16 + lane], (int)mysum);

        __syncthreads();   // tile[cur] reads done; tile[1-cur] stores done
        cur ^= 1;
    }
}

// ---------------------------------------------------------------------------
__global__ void k_final(const float* __restrict__ head_w,
                        const float* __restrict__ head_b,
                        float* __restrict__ out) {
    __shared__ float red[256];
    int tid = threadIdx.x;
    float acc = 0.f;
    for (int i = tid; i < T_*B_*CH_; i += 256) acc += (float)g_spk[i];
    red[tid] = acc; __syncthreads();
    for (int s = 128; s > 0; s >>= 1) { if (tid < s) red[tid] += red[tid+s]; __syncthreads(); }
    float totspk = red[0];
    __syncthreads();
    float e = 0.f;
    for (int i = tid; i < 1024; i += 256) e += g_epart[i];
    red[tid] = e; __syncthreads();
    for (int s = 128; s > 0; s >>= 1) { if (tid < s) red[tid] += red[tid+s]; __syncthreads(); }
    float etot = red[0];

    for (int idx = tid; idx < T_*B_*OUT_; idx += 256) {
        int o = idx % OUT_; int tb = idx / OUT_;
        const int* sp = &g_spk[tb*32];
        float s = 0.f;
        #pragma unroll
        for (int c = 0; c < 32; c++) s = fmaf((float)sp[c], head_w[c*OUT_ + o], s);
        out[80 + idx] = s * (1.0f/(float)(H_*W_)) + head_b[o];
    }
    __syncthreads();
    for (int idx = tid; idx < B_*OUT_; idx += 256) {
        int b = idx / OUT_, o = idx % OUT_;
        float s = 0.f;
        for (int t = 0; t < T_; t++) s += out[80 + ((t*B_ + b)*OUT_ + o)];
        out[idx] = s * (1.0f/(float)T_);
    }
    if (tid == 0) {
        out[80 + T_*B_*OUT_]     = totspk / ((float)T_*B_*H_*W_*CH_);
        out[80 + T_*B_*OUT_ + 1] = etot   / ((float)NIMG*H_*KX);
    }
}

// ---------------------------------------------------------------------------
extern "C" void kernel_launch(void* const* d_in, const int* in_sizes, int n_in,
                              void* d_out, int out_size) {
    const float* x     = (const float*)d_in[0];   // (16,8,224,224,3)
    const float* convw = (const float*)d_in[1];   // (3,3,4,32)
    const float* convb = (const float*)d_in[2];   // (32,)
    const float* headw = (const float*)d_in[3];   // (32,10)
    const float* headb = (const float*)d_in[4];   // (10,)
    float* out = (float*)d_out;

    k_init<<<16, 256>>>();
    { dim3 g(7,  NIMG);    k_stage1<<<g, 128>>>(x); }
    { dim3 g(4,  NIMG);    k_stage2<<<g, 224>>>(); }
    { dim3 g(98, B_, 2);   k_convlif<<<g, 256>>>(x, convw, convb); }
    k_final<<<1, 256>>>(headw, headb, out);
}